// round 15
// baseline (speedup 1.0000x reference)
#include <cuda_runtime.h>
#include <cstdint>

#define NG     1024
#define NB     444             // blocks: one wave (148 SM x 3)
#define NT     512
#define ITERS  30
#define FIXF   1024.0f
#define WSHIFT 21
#define WMASK  ((1u << WSHIFT) - 1u)

typedef unsigned long long ull;

// ---------------- device scratch (no allocations allowed) ----------------
__device__ uint32_t g_part[NG * NB];
__device__ float g_alphas[NG];
__device__ int   g_any;
__device__ unsigned g_cnt0, g_flag0;
__device__ unsigned g_cnt1, g_flag1;

// ---------------- 256-bit vector helpers (sm_100+: LDG.E.256 / STG.E.256) ----
struct f8 { float v[8]; };

__device__ __forceinline__ f8 ldg8_cs(const float* p) {
    f8 r;
    asm volatile("ld.global.cs.v8.f32 {%0,%1,%2,%3,%4,%5,%6,%7}, [%8];"
                 : "=f"(r.v[0]), "=f"(r.v[1]), "=f"(r.v[2]), "=f"(r.v[3]),
                   "=f"(r.v[4]), "=f"(r.v[5]), "=f"(r.v[6]), "=f"(r.v[7])
                 : "l"(p));
    return r;
}
__device__ __forceinline__ void stg8_cs(float* p, const f8& x) {
    asm volatile("st.global.cs.v8.f32 [%0], {%1,%2,%3,%4,%5,%6,%7,%8};"
                 :: "l"(p),
                    "f"(x.v[0]), "f"(x.v[1]), "f"(x.v[2]), "f"(x.v[3]),
                    "f"(x.v[4]), "f"(x.v[5]), "f"(x.v[6]), "f"(x.v[7])
                 : "memory");
}

// Monotonic-generation grid barrier; all NB blocks resident (444 = 148 x 3).
__device__ __forceinline__ void grid_barrier(unsigned* cnt, unsigned* flag, int tid) {
    __syncthreads();
    if (tid == 0) {
        __threadfence();
        unsigned gen = atomicAdd(flag, 0u);
        if (atomicAdd(cnt, 1u) == NB - 1u) {
            *cnt = 0u;
            __threadfence();
            atomicAdd(flag, 1u);
        } else {
            while (atomicAdd(flag, 0u) == gen) __nanosleep(40);
        }
    }
    __syncthreads();
}

__device__ __forceinline__ void samp_one(uint32_t* acc, float a, float yr, int g) {
    float s = fminf(fmaxf(__fdividef(a, yr), 0.9f), 1.1f);
    atomicAdd(&acc[g], (1u << WSHIFT) + (uint32_t)(s * FIXF + 0.5f));
}

__device__ __forceinline__ float out_fb(float a, float b, int g) {
    float yr = fmaxf(b, 1e-9f);
    float alpha = __ldg(&g_alphas[g]);
    float v = fmaf(alpha, yr, a);
    return fminf(fmaxf(v, 0.9f * yr), 1.1f * yr);
}

__global__ void __launch_bounds__(NT, 3) k_fused(
        const float* __restrict__ yraw, const float* __restrict__ yreal,
        const int* __restrict__ gid, float* __restrict__ out, int n) {
    __shared__ uint32_t acc[NG];
    __shared__ float sf[NT];
    __shared__ int   s_flag;
    __shared__ float s_T;
    const int tid = threadIdx.x;
    const int bid = blockIdx.x;
    const int wsel = (tid >> 5) & 7;              // this warp's sampling slot
    const int n8 = n >> 3;
    const int stride = NB * NT;

    // ====== phase 1: 256-bit clip stream + balanced temporal sampling ======
    for (int i = tid; i < NG; i += NT) acc[i] = 0u;
    if (bid == 0 && tid == 0) g_any = 0;
    __syncthreads();

    int i8 = bid * NT + tid;
    int k = 0;
    for (; i8 < n8; i8 += stride, k++) {
        const float* pa = yraw  + (size_t)i8 * 8;
        const float* pb = yreal + (size_t)i8 * 8;
        f8 a = ldg8_cs(pa);
        f8 b = ldg8_cs(pb);
        f8 o;
        #pragma unroll
        for (int e = 0; e < 8; e++) {
            float yr = fmaxf(b.v[e], 1e-9f);
            o.v[e] = fminf(fmaxf(a.v[e], 0.9f * yr), 1.1f * yr);
        }
        stg8_cs(out + (size_t)i8 * 8, o);
        if (((k ^ wsel) & 7) == 0) {              // every warp, 1/8 of its iters
            const int4* pg = (const int4*)(gid + (size_t)i8 * 8);
            int4 g0 = __ldcs(&pg[0]);
            int4 g1 = __ldcs(&pg[1]);
            samp_one(acc, a.v[0], fmaxf(b.v[0], 1e-9f), g0.x);
            samp_one(acc, a.v[1], fmaxf(b.v[1], 1e-9f), g0.y);
            samp_one(acc, a.v[2], fmaxf(b.v[2], 1e-9f), g0.z);
            samp_one(acc, a.v[3], fmaxf(b.v[3], 1e-9f), g0.w);
            samp_one(acc, a.v[4], fmaxf(b.v[4], 1e-9f), g1.x);
            samp_one(acc, a.v[5], fmaxf(b.v[5], 1e-9f), g1.y);
            samp_one(acc, a.v[6], fmaxf(b.v[6], 1e-9f), g1.z);
            samp_one(acc, a.v[7], fmaxf(b.v[7], 1e-9f), g1.w);
        }
    }
    {   // scalar tail (n not multiple of 8)
        int t = bid * NT + tid, tb = n8 * 8;
        if (t < n - tb) {
            float a = yraw[tb + t];
            float yr = fmaxf(yreal[tb + t], 1e-9f);
            out[tb + t] = fminf(fmaxf(a, 0.9f * yr), 1.1f * yr);
        }
    }
    __syncthreads();
    for (int g = tid; g < NG; g += NT)
        g_part[g * NB + bid] = acc[g];

    grid_barrier(&g_cnt0, &g_flag0, tid);

    // ====== phase 2: sampled feasibility; exact recheck when flagged ======
    ull* accl = (ull*)sf;
    for (int g = bid; g < NG; g += NB) {
        uint32_t c = 0u, f = 0u;
        for (int b = tid; b < NB; b += NT) {
            uint32_t v = g_part[g * NB + b];
            c += v >> WSHIFT;
            f += v & WMASK;
        }
        ull v = ((ull)c << 32) | (ull)f;
        for (int o = 16; o; o >>= 1) v += __shfl_down_sync(0xffffffffu, v, o);
        if ((tid & 31) == 0) accl[tid >> 5] = v;
        __syncthreads();
        if (tid == 0) {
            ull a = 0ull;
            #pragma unroll
            for (int w = 0; w < NT / 32; w++) a += accl[w];
            int   cs = (int)(a >> 32);
            float Ss = (float)(a & 0xffffffffull) * (1.0f / FIXF);
            float m  = (cs > 0) ? Ss / (float)cs : 0.0f;
            s_flag = (cs < 32 || m < 0.96f || m > 1.04f) ? 1 : 0;
            g_alphas[g] = 0.0f;
        }
        __syncthreads();
        if (!s_flag) continue;                    // sampled fast path

        // exact recheck: full scan for n_g and S0
        float s0 = 0.0f, cg = 0.0f;
        for (int i = tid; i < n; i += NT) {
            if (gid[i] == g) {
                float yr = fmaxf(yreal[i], 1e-9f);
                s0 += fminf(fmaxf(yraw[i] / yr, 0.9f), 1.1f);
                cg += 1.0f;
            }
        }
        sf[tid] = s0; __syncthreads();
        for (int d = NT / 2; d > 0; d >>= 1) { if (tid < d) sf[tid] += sf[tid + d]; __syncthreads(); }
        s0 = sf[0]; __syncthreads();
        sf[tid] = cg; __syncthreads();
        for (int d = NT / 2; d > 0; d >>= 1) { if (tid < d) sf[tid] += sf[tid + d]; __syncthreads(); }
        cg = sf[0]; __syncthreads();

        float L = 0.95f * cg, U = 1.05f * cg;
        bool infeas = (cg > 0.0f) && (s0 < L || s0 > U);
        if (tid == 0) {
            s_T = (s0 < L) ? L : U;
            if (infeas) atomicExch(&g_any, 1);
            s_flag = infeas ? 1 : 0;
        }
        __syncthreads();
        if (!s_flag) continue;                    // exactly feasible

        // exact bisection fallback
        float rmn = __int_as_float(0x7f800000);
        float rmx = __int_as_float(0xff800000);
        for (int i = tid; i < n; i += NT) {
            if (gid[i] == g) {
                float yr = fmaxf(yreal[i], 1e-9f);
                float r  = yraw[i] / yr;
                rmn = fminf(rmn, r);
                rmx = fmaxf(rmx, r);
            }
        }
        sf[tid] = rmn; __syncthreads();
        for (int d = NT / 2; d > 0; d >>= 1) { if (tid < d) sf[tid] = fminf(sf[tid], sf[tid + d]); __syncthreads(); }
        rmn = sf[0]; __syncthreads();
        sf[tid] = rmx; __syncthreads();
        for (int d = NT / 2; d > 0; d >>= 1) { if (tid < d) sf[tid] = fmaxf(sf[tid], sf[tid + d]); __syncthreads(); }
        rmx = sf[0]; __syncthreads();

        float lo = 0.9f - rmx - 1.0f;
        float hi = 1.1f - rmn + 1.0f;
        float T = s_T;
        float mid = lo;
        for (int it = 0; it < ITERS; ++it) {
            mid = 0.5f * (lo + hi);
            float p = 0.0f;
            for (int i = tid; i < n; i += NT) {
                if (gid[i] == g) {
                    float yr = fmaxf(yreal[i], 1e-9f);
                    float r  = yraw[i] / yr;
                    p += fminf(fmaxf(r + mid, 0.9f), 1.1f);
                }
            }
            sf[tid] = p; __syncthreads();
            for (int d = NT / 2; d > 0; d >>= 1) { if (tid < d) sf[tid] += sf[tid + d]; __syncthreads(); }
            float S2 = sf[0]; __syncthreads();
            if (S2 < T) lo = mid; else hi = mid;
        }
        if (tid == 0) g_alphas[g] = mid;
        __syncthreads();
    }

    grid_barrier(&g_cnt1, &g_flag1, tid);

    // ====== phase 3: rewrite pass — ONLY if some group truly infeasible ======
    if (g_any) {
        const float4* yraw4  = (const float4*)yraw;
        const float4* yreal4 = (const float4*)yreal;
        const int4*   gid4   = (const int4*)gid;
        float4*       out4   = (float4*)out;
        int n4 = n >> 2;
        const int st = NB * NT;
        for (int i = bid * NT + tid; i < n4; i += st) {
            float4 a = yraw4[i];
            float4 b = yreal4[i];
            int4   g = gid4[i];
            float4 o;
            o.x = out_fb(a.x, b.x, g.x);
            o.y = out_fb(a.y, b.y, g.y);
            o.z = out_fb(a.z, b.z, g.z);
            o.w = out_fb(a.w, b.w, g.w);
            out4[i] = o;
        }
        int t = bid * NT + tid, tb = n4 * 4;
        if (t < n - tb) out[tb + t] = out_fb(yraw[tb + t], yreal[tb + t], gid[tb + t]);
    }
}

// ---------------- launch ----------------
extern "C" void kernel_launch(void* const* d_in, const int* in_sizes, int n_in,
                              void* d_out, int out_size) {
    const float* yraw  = (const float*)d_in[0];
    const float* yreal = (const float*)d_in[1];
    const int*   gid   = (const int*)d_in[2];
    float* out = (float*)d_out;
    int n  = in_sizes[0];

    k_fused<<<NB, NT>>>(yraw, yreal, gid, out, n);
}

// round 16
// speedup vs baseline: 1.1115x; 1.1115x over previous
#include <cuda_runtime.h>
#include <cstdint>

#define NG     1024
#define NB     444             // blocks: one wave (148 SM x 3)
#define NT     512
#define ITERS  30
#define FIXF   1024.0f
#define WSHIFT 21
#define WMASK  ((1u << WSHIFT) - 1u)

typedef unsigned long long ull;

// ---------------- device scratch (no allocations allowed) ----------------
__device__ uint32_t g_part[NG * NB];
__device__ float g_alphas[NG];
__device__ int   g_any;
__device__ unsigned g_cnt0, g_flag0;
__device__ unsigned g_cnt1, g_flag1;

// Monotonic-generation grid barrier; all NB blocks resident (444 = 148 x 3).
__device__ __forceinline__ void grid_barrier(unsigned* cnt, unsigned* flag, int tid) {
    __syncthreads();
    if (tid == 0) {
        __threadfence();
        unsigned gen = atomicAdd(flag, 0u);
        if (atomicAdd(cnt, 1u) == NB - 1u) {
            *cnt = 0u;
            __threadfence();
            atomicAdd(flag, 1u);
        } else {
            while (atomicAdd(flag, 0u) == gen) __nanosleep(40);
        }
    }
    __syncthreads();
}

__device__ __forceinline__ void samp_one(uint32_t* acc, float a, float yr, int g) {
    float s = fminf(fmaxf(__fdividef(a, yr), 0.9f), 1.1f);
    atomicAdd(&acc[g], (1u << WSHIFT) + (uint32_t)(s * FIXF + 0.5f));
}

__device__ __forceinline__ float4 clip4(float4 a, float4 b) {
    float rx = fmaxf(b.x, 1e-9f), ry = fmaxf(b.y, 1e-9f);
    float rz = fmaxf(b.z, 1e-9f), rw = fmaxf(b.w, 1e-9f);
    float4 o;
    o.x = fminf(fmaxf(a.x, 0.9f * rx), 1.1f * rx);
    o.y = fminf(fmaxf(a.y, 0.9f * ry), 1.1f * ry);
    o.z = fminf(fmaxf(a.z, 0.9f * rz), 1.1f * rz);
    o.w = fminf(fmaxf(a.w, 0.9f * rw), 1.1f * rw);
    return o;
}

__device__ __forceinline__ void samp4(uint32_t* acc, float4 a, float4 b, int4 g) {
    samp_one(acc, a.x, fmaxf(b.x, 1e-9f), g.x);
    samp_one(acc, a.y, fmaxf(b.y, 1e-9f), g.y);
    samp_one(acc, a.z, fmaxf(b.z, 1e-9f), g.z);
    samp_one(acc, a.w, fmaxf(b.w, 1e-9f), g.w);
}

__device__ __forceinline__ float out_fb(float a, float b, int g) {
    float yr = fmaxf(b, 1e-9f);
    float alpha = __ldg(&g_alphas[g]);
    float v = fmaf(alpha, yr, a);
    return fminf(fmaxf(v, 0.9f * yr), 1.1f * yr);
}

__global__ void __launch_bounds__(NT, 3) k_fused(
        const float4* __restrict__ yraw4, const float4* __restrict__ yreal4,
        const int4* __restrict__ gid4, float4* __restrict__ out4, int n4,
        const float* __restrict__ yraw, const float* __restrict__ yreal,
        const int* __restrict__ gid, float* __restrict__ out, int n) {
    __shared__ uint32_t acc[NG];
    __shared__ float sf[NT];
    __shared__ int   s_flag;
    __shared__ float s_T;
    const int tid = threadIdx.x;
    const int bid = blockIdx.x;
    const int wsel = (tid >> 5) & 15;             // this warp's sampling slot (1/16)
    const int stride = NB * 2 * NT;               // 2 float4 per thread per iter

    // ====== phase 1: L2-friendly clip stream + balanced temporal sampling ======
    for (int i = tid; i < NG; i += NT) acc[i] = 0u;
    if (bid == 0 && tid == 0) g_any = 0;
    __syncthreads();

    int i0 = bid * 2 * NT + tid;
    int k = 0;
    for (; i0 + NT < n4; i0 += stride, k++) {
        int i1 = i0 + NT;
        // inputs: evict-NORMAL loads — keep resident in L2 across graph replays
        float4 a0 = yraw4[i0];
        float4 a1 = yraw4[i1];
        float4 b0 = yreal4[i0];
        float4 b1 = yreal4[i1];
        // output: evict-first stores — don't displace the inputs
        __stcs(&out4[i0], clip4(a0, b0));
        __stcs(&out4[i1], clip4(a1, b1));
        if (((k ^ wsel) & 15) == 0) {             // every warp, 1/16 of its iters
            int4 g0 = gid4[i0];
            int4 g1 = gid4[i1];
            samp4(acc, a0, b0, g0);
            samp4(acc, a1, b1, g1);
        }
    }
    // residual float4s
    for (; i0 < n4; i0 += NT) {
        float4 a = yraw4[i0];
        float4 b = yreal4[i0];
        __stcs(&out4[i0], clip4(a, b));
        if (((k ^ wsel) & 15) == 0) {
            int4 g = gid4[i0];
            samp4(acc, a, b, g);
        }
    }
    {   // scalar tail (n not multiple of 4)
        int t = bid * NT + tid, tb = n4 * 4;
        if (t < n - tb) {
            float a = yraw[tb + t];
            float yr = fmaxf(yreal[tb + t], 1e-9f);
            out[tb + t] = fminf(fmaxf(a, 0.9f * yr), 1.1f * yr);
        }
    }
    __syncthreads();
    for (int g = tid; g < NG; g += NT)
        g_part[g * NB + bid] = acc[g];

    grid_barrier(&g_cnt0, &g_flag0, tid);

    // ====== phase 2: sampled feasibility; exact recheck when flagged ======
    ull* accl = (ull*)sf;
    for (int g = bid; g < NG; g += NB) {
        uint32_t c = 0u, f = 0u;
        for (int b = tid; b < NB; b += NT) {
            uint32_t v = g_part[g * NB + b];
            c += v >> WSHIFT;
            f += v & WMASK;
        }
        ull v = ((ull)c << 32) | (ull)f;
        for (int o = 16; o; o >>= 1) v += __shfl_down_sync(0xffffffffu, v, o);
        if ((tid & 31) == 0) accl[tid >> 5] = v;
        __syncthreads();
        if (tid == 0) {
            ull a = 0ull;
            #pragma unroll
            for (int w = 0; w < NT / 32; w++) a += accl[w];
            int   cs = (int)(a >> 32);
            float Ss = (float)(a & 0xffffffffull) * (1.0f / FIXF);
            float m  = (cs > 0) ? Ss / (float)cs : 0.0f;
            s_flag = (cs < 32 || m < 0.96f || m > 1.04f) ? 1 : 0;
            g_alphas[g] = 0.0f;
        }
        __syncthreads();
        if (!s_flag) continue;                    // sampled fast path

        // exact recheck: full scan for n_g and S0
        float s0 = 0.0f, cg = 0.0f;
        for (int i = tid; i < n; i += NT) {
            if (gid[i] == g) {
                float yr = fmaxf(yreal[i], 1e-9f);
                s0 += fminf(fmaxf(yraw[i] / yr, 0.9f), 1.1f);
                cg += 1.0f;
            }
        }
        sf[tid] = s0; __syncthreads();
        for (int d = NT / 2; d > 0; d >>= 1) { if (tid < d) sf[tid] += sf[tid + d]; __syncthreads(); }
        s0 = sf[0]; __syncthreads();
        sf[tid] = cg; __syncthreads();
        for (int d = NT / 2; d > 0; d >>= 1) { if (tid < d) sf[tid] += sf[tid + d]; __syncthreads(); }
        cg = sf[0]; __syncthreads();

        float L = 0.95f * cg, U = 1.05f * cg;
        bool infeas = (cg > 0.0f) && (s0 < L || s0 > U);
        if (tid == 0) {
            s_T = (s0 < L) ? L : U;
            if (infeas) atomicExch(&g_any, 1);
            s_flag = infeas ? 1 : 0;
        }
        __syncthreads();
        if (!s_flag) continue;                    // exactly feasible

        // exact bisection fallback
        float rmn = __int_as_float(0x7f800000);
        float rmx = __int_as_float(0xff800000);
        for (int i = tid; i < n; i += NT) {
            if (gid[i] == g) {
                float yr = fmaxf(yreal[i], 1e-9f);
                float r  = yraw[i] / yr;
                rmn = fminf(rmn, r);
                rmx = fmaxf(rmx, r);
            }
        }
        sf[tid] = rmn; __syncthreads();
        for (int d = NT / 2; d > 0; d >>= 1) { if (tid < d) sf[tid] = fminf(sf[tid], sf[tid + d]); __syncthreads(); }
        rmn = sf[0]; __syncthreads();
        sf[tid] = rmx; __syncthreads();
        for (int d = NT / 2; d > 0; d >>= 1) { if (tid < d) sf[tid] = fmaxf(sf[tid], sf[tid + d]); __syncthreads(); }
        rmx = sf[0]; __syncthreads();

        float lo = 0.9f - rmx - 1.0f;
        float hi = 1.1f - rmn + 1.0f;
        float T = s_T;
        float mid = lo;
        for (int it = 0; it < ITERS; ++it) {
            mid = 0.5f * (lo + hi);
            float p = 0.0f;
            for (int i = tid; i < n; i += NT) {
                if (gid[i] == g) {
                    float yr = fmaxf(yreal[i], 1e-9f);
                    float r  = yraw[i] / yr;
                    p += fminf(fmaxf(r + mid, 0.9f), 1.1f);
                }
            }
            sf[tid] = p; __syncthreads();
            for (int d = NT / 2; d > 0; d >>= 1) { if (tid < d) sf[tid] += sf[tid + d]; __syncthreads(); }
            float S2 = sf[0]; __syncthreads();
            if (S2 < T) lo = mid; else hi = mid;
        }
        if (tid == 0) g_alphas[g] = mid;
        __syncthreads();
    }

    grid_barrier(&g_cnt1, &g_flag1, tid);

    // ====== phase 3: rewrite pass — ONLY if some group truly infeasible ======
    if (g_any) {
        const int st = NB * NT;
        for (int i = bid * NT + tid; i < n4; i += st) {
            float4 a = yraw4[i];
            float4 b = yreal4[i];
            int4   g = gid4[i];
            float4 o;
            o.x = out_fb(a.x, b.x, g.x);
            o.y = out_fb(a.y, b.y, g.y);
            o.z = out_fb(a.z, b.z, g.z);
            o.w = out_fb(a.w, b.w, g.w);
            out4[i] = o;
        }
        int t = bid * NT + tid, tb = n4 * 4;
        if (t < n - tb) out[tb + t] = out_fb(yraw[tb + t], yreal[tb + t], gid[tb + t]);
    }
}

// ---------------- launch ----------------
extern "C" void kernel_launch(void* const* d_in, const int* in_sizes, int n_in,
                              void* d_out, int out_size) {
    const float* yraw  = (const float*)d_in[0];
    const float* yreal = (const float*)d_in[1];
    const int*   gid   = (const int*)d_in[2];
    float* out = (float*)d_out;
    int n  = in_sizes[0];
    int n4 = n >> 2;

    k_fused<<<NB, NT>>>((const float4*)yraw, (const float4*)yreal, (const int4*)gid,
                        (float4*)d_out, n4, yraw, yreal, gid, out, n);
}